// round 2
// baseline (speedup 1.0000x reference)
#include <cuda_runtime.h>
#include <cstdint>

// ---------------- problem dims ----------------
#define N_NODES 61440
#define NEDGE   491520
#define BATCH   2048
#define TT      30
#define INCH    12
#define FCF     3840     // 128*30
#define FCO     72

// ---------------- device scratch ----------------
__device__ float g_deg [N_NODES];
__device__ float g_dinv[N_NODES];
__device__ float g_h   [N_NODES * 12];
__device__ float g_x0  [N_NODES * 12];            // [B][12][30]
__device__ float g_x1  [BATCH * 128 * TT];        // [B][128][30]
__device__ float g_x2  [BATCH * 512 * TT];        // [B][512][30]
__device__ float g_x3  [BATCH * 128 * TT];        // [B][128][30] (relu'd)
__device__ float g_wt0 [12  * 4 * 128];           // [ic][j][oc], j=0..2 conv, j=3 down
__device__ float g_wt1 [128 * 4 * 512];
__device__ float g_wt2 [512 * 4 * 128];
__device__ float g_fcwT[FCF * FCO];               // [f][o]
__device__ int   g_eflag[1];                      // 1 => edge_index is int32

// ---------------- init / dtype detect ----------------
__global__ void k_init() {
    int i = blockIdx.x * blockDim.x + threadIdx.x;
    if (i < N_NODES * 12) g_x0[i] = 0.0f;
    if (i < N_NODES)      g_deg[i] = 1.0f;     // self-loop
    if (i == 0)           g_eflag[0] = 0;
}

__global__ void k_detect(const long long* __restrict__ ep) {
    int i = blockIdx.x * blockDim.x + threadIdx.x;
    if (i < 2048) {
        long long v = ep[i];
        if (v < 0 || v >= N_NODES) atomicOr(g_eflag, 1);
    }
}

__device__ __forceinline__ void load_edge(const void* ep, int e, int& s, int& d) {
    if (g_eflag[0]) {
        const int* p = (const int*)ep;
        s = p[e]; d = p[NEDGE + e];
    } else {
        const long long* p = (const long long*)ep;
        s = (int)p[e]; d = (int)p[NEDGE + e];
    }
}

// ---------------- weight transposes ----------------
__global__ void k_twt(const float* __restrict__ cw, const float* __restrict__ dw,
                      float* __restrict__ wt, int OC, int IC) {
    int id = blockIdx.x * blockDim.x + threadIdx.x;
    int tot = OC * IC * 4;
    if (id >= tot) return;
    int oc = id % OC;
    int r  = id / OC;
    int j  = r % 4;
    int ic = r / 4;
    wt[id] = (j < 3) ? cw[(oc * IC + ic) * 3 + j] : dw[oc * IC + ic];
}

__global__ void k_tfc(const float* __restrict__ fw, float* __restrict__ wT) {
    int id = blockIdx.x * blockDim.x + threadIdx.x;
    if (id >= FCF * FCO) return;
    int o = id % FCO;
    int f = id / FCO;
    wT[id] = fw[o * FCF + f];
}

// ---------------- GCN ----------------
__global__ void k_deg(const void* __restrict__ ep) {
    int e = blockIdx.x * blockDim.x + threadIdx.x;
    if (e >= NEDGE) return;
    int s, d;
    load_edge(ep, e, s, d);
    atomicAdd(&g_deg[d], 1.0f);
}

__global__ void k_h(const float* __restrict__ x, const float* __restrict__ gw) {
    int n = blockIdx.x * blockDim.x + threadIdx.x;
    if (n >= N_NODES) return;
    const float4* xp = (const float4*)(x + (size_t)n * 12);
    float4 a = xp[0], b = xp[1], c = xp[2];
    float xv[12] = {a.x,a.y,a.z,a.w, b.x,b.y,b.z,b.w, c.x,c.y,c.z,c.w};
    #pragma unroll
    for (int o = 0; o < 12; ++o) {
        float acc = 0.0f;
        #pragma unroll
        for (int i = 0; i < 12; ++i)
            acc = fmaf(xv[i], __ldg(&gw[o * 12 + i]), acc);
        g_h[n * 12 + o] = acc;
    }
    g_dinv[n] = rsqrtf(g_deg[n]);
}

__global__ void k_scatter(const void* __restrict__ ep) {
    int e = blockIdx.x * blockDim.x + threadIdx.x;
    if (e >= NEDGE) return;
    int s, d;
    load_edge(ep, e, s, d);
    float nm = g_dinv[s] * g_dinv[d];
    int base = (d / 30) * (12 * TT) + (d % 30);
    const float4* hp = (const float4*)(g_h + (size_t)s * 12);
    float4 a = hp[0], b = hp[1], c = hp[2];
    float hv[12] = {a.x,a.y,a.z,a.w, b.x,b.y,b.z,b.w, c.x,c.y,c.z,c.w};
    #pragma unroll
    for (int cch = 0; cch < 12; ++cch)
        atomicAdd(&g_x0[base + cch * TT], nm * hv[cch]);
}

__global__ void k_self(const float* __restrict__ gb) {
    int n = blockIdx.x * blockDim.x + threadIdx.x;
    if (n >= N_NODES) return;
    float di = g_dinv[n];
    float nm = di * di;
    int base = (n / 30) * (12 * TT) + (n % 30);
    #pragma unroll
    for (int c = 0; c < 12; ++c)
        g_x0[base + c * TT] += nm * g_h[n * 12 + c] + __ldg(&gb[c]);
}

// ---------------- TCN block (conv k=3 dilated causal + 1x1 downsample, fused) ----------------
// thread <-> one output channel; accumulate all 30 timesteps in registers.
template<int IC, int ICC, int DIL, int OCT, int OCTOT>
__global__ __launch_bounds__(OCT)
void tcn_kernel(const float* __restrict__ Xin, const float* __restrict__ wt,
                const float* __restrict__ cb, const float* __restrict__ db,
                float* __restrict__ Xout) {
    __shared__ float xs[ICC * TT];
    int b  = blockIdx.x;
    int oc = blockIdx.y * OCT + threadIdx.x;

    float accC[TT], accR[TT];
    #pragma unroll
    for (int t = 0; t < TT; ++t) { accC[t] = 0.0f; accR[t] = 0.0f; }

    #pragma unroll 1
    for (int ch = 0; ch < IC / ICC; ++ch) {
        __syncthreads();
        const float* src = Xin + ((size_t)b * IC + ch * ICC) * TT;
        for (int i = threadIdx.x; i < ICC * TT; i += OCT) xs[i] = src[i];
        __syncthreads();

        #pragma unroll 2
        for (int icl = 0; icl < ICC; ++icl) {
            const float* wp = wt + ((size_t)(ch * ICC + icl) * 4) * OCTOT + oc;
            float w0 = __ldg(wp);
            float w1 = __ldg(wp + OCTOT);
            float w2 = __ldg(wp + 2 * OCTOT);
            float wd = __ldg(wp + 3 * OCTOT);
            #pragma unroll
            for (int t = 0; t < TT; ++t) {
                float xv = xs[icl * TT + t];
                accC[t] = fmaf(w2, xv, accC[t]);
                if (t + DIL < TT)     accC[t + DIL]     = fmaf(w1, xv, accC[t + DIL]);
                if (t + 2 * DIL < TT) accC[t + 2 * DIL] = fmaf(w0, xv, accC[t + 2 * DIL]);
                accR[t] = fmaf(wd, xv, accR[t]);
            }
        }
    }

    float bc = __ldg(&cb[oc]);
    float bd = __ldg(&db[oc]);
    float* dst = Xout + ((size_t)b * OCTOT + oc) * TT;
    #pragma unroll
    for (int t = 0; t < TT; ++t) {
        float o1 = fmaxf(accC[t] + bc, 0.0f);
        float v  = fmaxf(o1 + accR[t] + bd, 0.0f);
        dst[t] = v;
    }
}

// ---------------- FC: out[b][o] = sum_f X3[b][f] * fcwT[f][o] + fb[o] ----------------
// block (72,4): x = output channel o, y = q (f-interleave split). 8 batches per CTA.
#define FC_NB 8
#define FC_CH 480
__global__ __launch_bounds__(288)
void fc_kernel(const float* __restrict__ X, const float* __restrict__ wT,
               const float* __restrict__ fb, float* __restrict__ out) {
    __shared__ float xsf[FC_CH * FC_NB];          // [f_local][b]
    __shared__ float red[4 * FC_NB * FCO];        // [q][b][o]
    int o   = threadIdx.x;
    int q   = threadIdx.y;
    int tid = q * FCO + o;
    int b0  = blockIdx.x * FC_NB;

    float acc[FC_NB];
    #pragma unroll
    for (int i = 0; i < FC_NB; ++i) acc[i] = 0.0f;

    #pragma unroll 1
    for (int ch = 0; ch < FCF / FC_CH; ++ch) {
        __syncthreads();
        for (int i = tid; i < FC_CH * FC_NB; i += 288) {
            int bb = i / FC_CH;
            int fl = i % FC_CH;
            xsf[fl * FC_NB + bb] = X[(size_t)(b0 + bb) * FCF + ch * FC_CH + fl];
        }
        __syncthreads();
        #pragma unroll 4
        for (int i = 0; i < FC_CH / 4; ++i) {
            int fl = i * 4 + q;
            float w = __ldg(&wT[(size_t)(ch * FC_CH + fl) * FCO + o]);
            const float4* xp = (const float4*)&xsf[fl * FC_NB];
            float4 xa = xp[0], xb = xp[1];
            acc[0] = fmaf(w, xa.x, acc[0]);
            acc[1] = fmaf(w, xa.y, acc[1]);
            acc[2] = fmaf(w, xa.z, acc[2]);
            acc[3] = fmaf(w, xa.w, acc[3]);
            acc[4] = fmaf(w, xb.x, acc[4]);
            acc[5] = fmaf(w, xb.y, acc[5]);
            acc[6] = fmaf(w, xb.z, acc[6]);
            acc[7] = fmaf(w, xb.w, acc[7]);
        }
    }
    #pragma unroll
    for (int bb = 0; bb < FC_NB; ++bb)
        red[(q * FC_NB + bb) * FCO + o] = acc[bb];
    __syncthreads();
    for (int idx = tid; idx < FC_NB * FCO; idx += 288) {
        int bb = idx / FCO;
        int oo = idx % FCO;
        float s = red[(0 * FC_NB + bb) * FCO + oo]
                + red[(1 * FC_NB + bb) * FCO + oo]
                + red[(2 * FC_NB + bb) * FCO + oo]
                + red[(3 * FC_NB + bb) * FCO + oo];
        out[(size_t)(b0 + bb) * FCO + oo] = s + __ldg(&fb[oo]);
    }
}

// ---------------- launch ----------------
extern "C" void kernel_launch(void* const* d_in, const int* in_sizes, int n_in,
                              void* d_out, int out_size) {
    const float* x       = (const float*)d_in[0];
    const void*  eidx    = d_in[1];
    const float* gcn_w   = (const float*)d_in[2];
    const float* gcn_b   = (const float*)d_in[3];
    const float* conv_w0 = (const float*)d_in[4];
    const float* conv_b0 = (const float*)d_in[5];
    const float* down_w0 = (const float*)d_in[6];
    const float* down_b0 = (const float*)d_in[7];
    const float* conv_w1 = (const float*)d_in[8];
    const float* conv_b1 = (const float*)d_in[9];
    const float* down_w1 = (const float*)d_in[10];
    const float* down_b1 = (const float*)d_in[11];
    const float* conv_w2 = (const float*)d_in[12];
    const float* conv_b2 = (const float*)d_in[13];
    const float* down_w2 = (const float*)d_in[14];
    const float* down_b2 = (const float*)d_in[15];
    const float* fc_w    = (const float*)d_in[16];
    const float* fc_b    = (const float*)d_in[17];
    float* out = (float*)d_out;

    float *p_wt0, *p_wt1, *p_wt2, *p_fcwT;
    cudaGetSymbolAddress((void**)&p_wt0,  g_wt0);
    cudaGetSymbolAddress((void**)&p_wt1,  g_wt1);
    cudaGetSymbolAddress((void**)&p_wt2,  g_wt2);
    cudaGetSymbolAddress((void**)&p_fcwT, g_fcwT);
    float *p_x0, *p_x1, *p_x2, *p_x3;
    cudaGetSymbolAddress((void**)&p_x0, g_x0);
    cudaGetSymbolAddress((void**)&p_x1, g_x1);
    cudaGetSymbolAddress((void**)&p_x2, g_x2);
    cudaGetSymbolAddress((void**)&p_x3, g_x3);

    // init + edge dtype detect
    k_init<<<(N_NODES * 12 + 255) / 256, 256>>>();
    k_detect<<<8, 256>>>((const long long*)eidx);

    // weight prep (independent)
    k_twt<<<(128 * 12 * 4 + 255) / 256, 256>>>(conv_w0, down_w0, p_wt0, 128, 12);
    k_twt<<<(512 * 128 * 4 + 255) / 256, 256>>>(conv_w1, down_w1, p_wt1, 512, 128);
    k_twt<<<(128 * 512 * 4 + 255) / 256, 256>>>(conv_w2, down_w2, p_wt2, 128, 512);
    k_tfc<<<(FCF * FCO + 255) / 256, 256>>>(fc_w, p_fcwT);

    // GCN
    k_deg<<<(NEDGE + 255) / 256, 256>>>(eidx);
    k_h<<<(N_NODES + 127) / 128, 128>>>(x, gcn_w);
    k_scatter<<<(NEDGE + 127) / 128, 128>>>(eidx);
    k_self<<<(N_NODES + 127) / 128, 128>>>(gcn_b);

    // TCN blocks
    tcn_kernel<12, 12, 1, 128, 128><<<dim3(BATCH, 1), 128>>>(p_x0, p_wt0, conv_b0, down_b0, p_x1);
    tcn_kernel<128, 128, 3, 256, 512><<<dim3(BATCH, 2), 256>>>(p_x1, p_wt1, conv_b1, down_b1, p_x2);
    tcn_kernel<512, 128, 9, 128, 128><<<dim3(BATCH, 1), 128>>>(p_x2, p_wt2, conv_b2, down_b2, p_x3);

    // FC
    fc_kernel<<<BATCH / FC_NB, dim3(FCO, 4)>>>(p_x3, p_fcwT, fc_b, out);
}